// round 4
// baseline (speedup 1.0000x reference)
#include <cuda_runtime.h>
#include <cuda_bf16.h>
#include <cstdint>

// Problem constants
#define BB   64
#define NN   4096
#define DDIM 512
#define AATT 128
#define TILE 128
#define NTILES 32            // NN / TILE
#define NCTA  2048           // BB * NTILES
#define KCH   8              // DDIM / 64

// ---------------- SMEM layout ----------------------------------------------------
#define SM_WS   0                     // 4 floats: per-warp w sums
#define SM_Q    64                    // 128 floats q_att[b]
#define SM_WP   576                   // 128 floats W_p
#define SM_P    1088                  // 128 floats logit accumulators
#define SM_W    1600                  // 128 floats exp weights
#define SM_A    2176                  // 8 subtiles x 16KB = 128KB (v_I bf16, SW128; epilogue reuse)
#define SM_A32  (SM_A + 131072)       // 32KB: current chunk, tf32, xor-swizzled
#define SM_B32  (SM_A32 + 32768)      // 32KB: current chunk of W_I^T, tf32, xor-swizzled
#define SMEM_TOTAL (SM_B32 + 32768)   // 198784 bytes -> 1 CTA/SM

// ---------------- device scratch (no allocation allowed) ------------------------
__device__ float g_qatt[BB * AATT];
__device__ __align__(16) uint32_t g_wit32[KCH * 8192];       // W_I^T tf32, pre-swizzled (256KB)
__device__ float g_partial_acc[(size_t)NCTA * DDIM];         // 4 MB
__device__ float g_partial_S[NCTA];

// ---------------- helpers --------------------------------------------------------
__device__ __forceinline__ uint32_t smem_u32(const void* p) {
    uint32_t a;
    asm("{ .reg .u64 t; cvta.to.shared.u64 t, %1; cvt.u32.u64 %0, t; }" : "=r"(a) : "l"(p));
    return a;
}
__device__ __forceinline__ float tanha(float x) {
    float y; asm("tanh.approx.f32 %0, %1;" : "=f"(y) : "f"(x)); return y;
}
__device__ __forceinline__ uint32_t f2tf32(float f) {
    uint32_t r; asm("cvt.rna.tf32.f32 %0, %1;" : "=r"(r) : "f"(f)); return r;
}
__device__ __forceinline__ uint32_t lds32(uint32_t addr) {
    uint32_t v; asm volatile("ld.shared.b32 %0, [%1];" : "=r"(v) : "r"(addr)); return v;
}
__device__ __forceinline__ uint32_t sw128(uint32_t off) { return off ^ ((off >> 3) & 0x70); }
// word-index swizzle for tf32 tiles (stride 64 words): distinct banks for frag loads
__device__ __forceinline__ uint32_t swv(uint32_t row, uint32_t k) {
    return (row * 64u + k) ^ ((row & 7u) << 2);
}

// ---------------- prep kernels ----------------------------------------------------
// q_att[b][a] = tanh(v_Q[b,:] . W_Q[:,a] + b_Q[a])   (precise tanhf; tiny kernel)
__global__ void prep_qatt(const float* __restrict__ vQ, const float* __restrict__ WQ,
                          const float* __restrict__ bQ) {
    int b = blockIdx.x, a = threadIdx.x;
    const float* vq = vQ + (size_t)b * DDIM;
    float s = bQ[a];
#pragma unroll 8
    for (int k = 0; k < DDIM; ++k) s = fmaf(vq[k], WQ[(size_t)k * AATT + a], s);
    g_qatt[b * AATT + a] = tanhf(s);
}

// W_I^T -> tf32, pre-swizzled: chunk c holds rows a=0..127 (ATT) x k in [64c,64c+64)
__global__ void prep_wit(const float* __restrict__ WI) {
    int idx = blockIdx.x * blockDim.x + threadIdx.x;   // 0..65535
    int k = idx >> 7, a = idx & 127;
    float v = WI[(size_t)k * AATT + a];
    int sub = k >> 6;
    g_wit32[sub * 8192 + swv((uint32_t)a, (uint32_t)(k & 63))] = f2tf32(v);
}

// ---------------- main kernel ------------------------------------------------------
__global__ __launch_bounds__(256, 1)
void main_kernel(const float* __restrict__ vI, const float* __restrict__ Wp,
                 float* __restrict__ out_p) {
    extern __shared__ char smem[];
    float* q_s  = (float*)(smem + SM_Q);
    float* wp_s = (float*)(smem + SM_WP);
    float* p_s  = (float*)(smem + SM_P);
    float* w_s  = (float*)(smem + SM_W);
    float* ws4  = (float*)(smem + SM_WS);

    const int tid  = threadIdx.x, wid = tid >> 5, lane = tid & 31;
    const int bidx = blockIdx.x;
    const int b    = bidx >> 5;
    const int n0   = (bidx & 31) * TILE;

    if (tid < AATT) {
        q_s[tid]  = g_qatt[b * AATT + tid];
        wp_s[tid] = Wp[tid];
        p_s[tid]  = 0.f;
    }

    // Per-thread A-load mapping: thread t loads row = t/2, 32 contiguous floats
    const int arow = tid >> 1, ahalf = tid & 1;
    const float* asrc = vI + ((size_t)b * NN + n0 + arow) * DDIM + ahalf * 32;

    // prefetch chunk 0 into registers
    float4 pf[8];
#pragma unroll
    for (int j = 0; j < 8; ++j) pf[j] = ((const float4*)asrc)[j];

    const int wm = wid >> 2, wn = wid & 3;     // 2 (M) x 4 (N) warp grid
    const int g = lane >> 2, t4 = lane & 3;    // mma group / thread-in-group
    float acc[4][4][4];
#pragma unroll
    for (int mt = 0; mt < 4; ++mt)
#pragma unroll
        for (int nt = 0; nt < 4; ++nt)
#pragma unroll
            for (int r = 0; r < 4; ++r) acc[mt][nt][r] = 0.f;

    const uint32_t sbase = smem_u32(smem);
    const uint32_t a32b  = sbase + SM_A32;
    const uint32_t b32b  = sbase + SM_B32;

    // ---- mainloop: 8 K-chunks of 64 ----
    for (int c = 0; c < KCH; ++c) {
        // (a) bf16 copy of A chunk -> resident tile (for epilogue 2)
        char* adst = smem + SM_A + c * 16384;
#pragma unroll
        for (int j = 0; j < 4; ++j) {
            __nv_bfloat162 h0 = __floats2bfloat162_rn(pf[2*j].x, pf[2*j].y);
            __nv_bfloat162 h1 = __floats2bfloat162_rn(pf[2*j].z, pf[2*j].w);
            __nv_bfloat162 h2 = __floats2bfloat162_rn(pf[2*j+1].x, pf[2*j+1].y);
            __nv_bfloat162 h3 = __floats2bfloat162_rn(pf[2*j+1].z, pf[2*j+1].w);
            uint4 pk;
            pk.x = *(uint32_t*)&h0; pk.y = *(uint32_t*)&h1;
            pk.z = *(uint32_t*)&h2; pk.w = *(uint32_t*)&h3;
            uint32_t off = (uint32_t)(arow * 128 + ahalf * 64 + j * 16);
            *(uint4*)(adst + sw128(off)) = pk;
        }
        // (b) tf32 copy of A chunk -> A32 buffer (xor-swizzled, STS.128)
#pragma unroll
        for (int j = 0; j < 8; ++j) {
            uint4 pk;
            pk.x = f2tf32(pf[j].x); pk.y = f2tf32(pf[j].y);
            pk.z = f2tf32(pf[j].z); pk.w = f2tf32(pf[j].w);
            uint32_t w = (uint32_t)(arow * 64 + ahalf * 32 + j * 4);
            uint32_t sw = w ^ ((uint32_t)(arow & 7) << 2);
            *(uint4*)(smem + SM_A32 + (sw << 2)) = pk;
        }
        // (c) copy B chunk (pre-swizzled tf32, L2-resident)
        {
            const uint4* bg = (const uint4*)(g_wit32 + c * 8192);
            uint4* bs = (uint4*)(smem + SM_B32);
#pragma unroll
            for (int it = 0; it < 8; ++it) bs[tid + it * 256] = bg[tid + it * 256];
        }
        __syncthreads();

        // prefetch next A chunk (overlaps with MMAs below)
        if (c < KCH - 1) {
            const float4* nsrc = (const float4*)(asrc + (c + 1) * 64);
#pragma unroll
            for (int j = 0; j < 8; ++j) pf[j] = nsrc[j];
        }

        // (d) MMA over this chunk: 8 k8-steps, tf32
#pragma unroll
        for (int kk = 0; kk < 8; ++kk) {
            const uint32_t k0 = (uint32_t)(kk * 8 + t4);
            uint32_t af[4][4];
#pragma unroll
            for (int mt = 0; mt < 4; ++mt) {
                uint32_t r0 = (uint32_t)(wm * 64 + mt * 16 + g);
                af[mt][0] = lds32(a32b + (swv(r0,     k0)     << 2));
                af[mt][1] = lds32(a32b + (swv(r0 + 8, k0)     << 2));
                af[mt][2] = lds32(a32b + (swv(r0,     k0 + 4) << 2));
                af[mt][3] = lds32(a32b + (swv(r0 + 8, k0 + 4) << 2));
            }
            uint32_t bfr[4][2];
#pragma unroll
            for (int nt = 0; nt < 4; ++nt) {
                uint32_t n = (uint32_t)(wn * 32 + nt * 8 + g);
                bfr[nt][0] = lds32(b32b + (swv(n, k0)     << 2));
                bfr[nt][1] = lds32(b32b + (swv(n, k0 + 4) << 2));
            }
#pragma unroll
            for (int mt = 0; mt < 4; ++mt)
#pragma unroll
                for (int nt = 0; nt < 4; ++nt)
                    asm volatile(
                        "mma.sync.aligned.m16n8k8.row.col.f32.tf32.tf32.f32 "
                        "{%0,%1,%2,%3}, {%4,%5,%6,%7}, {%8,%9}, {%0,%1,%2,%3};"
                        : "+f"(acc[mt][nt][0]), "+f"(acc[mt][nt][1]),
                          "+f"(acc[mt][nt][2]), "+f"(acc[mt][nt][3])
                        : "r"(af[mt][0]), "r"(af[mt][1]), "r"(af[mt][2]), "r"(af[mt][3]),
                          "r"(bfr[nt][0]), "r"(bfr[nt][1]));
        }
        __syncthreads();   // MMA(c) done -> safe to overwrite A32/B32 next iter
    }

    // ---- epilogue 1: logits from accumulators -> p_s[row] via quad-reduce + atomics ----
#pragma unroll
    for (int mt = 0; mt < 4; ++mt) {
        float s0 = 0.f, s1 = 0.f;
#pragma unroll
        for (int nt = 0; nt < 4; ++nt) {
            int col = wn * 32 + nt * 8 + t4 * 2;
            float q0 = q_s[col], q1 = q_s[col + 1];
            float w0 = wp_s[col], w1 = wp_s[col + 1];
            s0 = fmaf(w0, tanha(tanha(acc[mt][nt][0]) + q0), s0);
            s0 = fmaf(w1, tanha(tanha(acc[mt][nt][1]) + q1), s0);
            s1 = fmaf(w0, tanha(tanha(acc[mt][nt][2]) + q0), s1);
            s1 = fmaf(w1, tanha(tanha(acc[mt][nt][3]) + q1), s1);
        }
        s0 += __shfl_xor_sync(0xffffffffu, s0, 1);
        s0 += __shfl_xor_sync(0xffffffffu, s0, 2);
        s1 += __shfl_xor_sync(0xffffffffu, s1, 1);
        s1 += __shfl_xor_sync(0xffffffffu, s1, 2);
        if (t4 == 0) {
            int r = wm * 64 + mt * 16 + g;
            atomicAdd(&p_s[r], s0);
            atomicAdd(&p_s[r + 8], s1);
        }
    }
    __syncthreads();

    if (tid < 128) {
        float w = __expf(p_s[tid]);          // logits bounded by ||W_p||_1 ~ 9: no max pass
        out_p[(size_t)b * NN + n0 + tid] = w;  // unnormalized; reduce kernel scales
        w_s[tid] = w;
        float s = w;
#pragma unroll
        for (int o = 16; o; o >>= 1) s += __shfl_xor_sync(0xffffffffu, s, o);
        if (lane == 0) ws4[wid] = s;
    }
    __syncthreads();
    if (tid == 0) g_partial_S[bidx] = ws4[0] + ws4[1] + ws4[2] + ws4[3];

    // ---- epilogue 2: weighted v-sum from resident bf16 A tile (all 8 warps) ----
    {
        int d0 = tid * 2;
        int sub = d0 >> 6;                       // which 64-col K-chunk
        uint32_t cb = (uint32_t)((d0 & 63) * 2); // byte col within chunk
        const char* abase = smem + SM_A + sub * 16384;
        float a0 = 0.f, a1 = 0.f;
#pragma unroll 8
        for (int r = 0; r < TILE; ++r) {
            uint32_t off = (uint32_t)(r * 128) + cb;
            __nv_bfloat162 v2 = *(const __nv_bfloat162*)(abase + sw128(off));
            float2 f = __bfloat1622float2(v2);
            float w = w_s[r];
            a0 = fmaf(w, f.x, a0);
            a1 = fmaf(w, f.y, a1);
        }
        *(float2*)(g_partial_acc + (size_t)bidx * DDIM + d0) = make_float2(a0, a1);
    }
}

// ---------------- reduce: S, u, normalize p ---------------------------------------
__global__ void reduce_kernel(const float* __restrict__ vQ, float* __restrict__ out_p,
                              float* __restrict__ out_u) {
    int b = blockIdx.x, tid = threadIdx.x;
    __shared__ float sInv;
    if (tid < 32) {
        float s = g_partial_S[b * 32 + tid];
#pragma unroll
        for (int o = 16; o; o >>= 1) s += __shfl_xor_sync(0xffffffffu, s, o);
        if (tid == 0) sInv = 1.0f / s;
    }
    __syncthreads();
    float inv = sInv;
    float acc = 0.f;
#pragma unroll 8
    for (int t = 0; t < 32; ++t)
        acc += g_partial_acc[(size_t)(b * 32 + t) * DDIM + tid];
    out_u[(size_t)b * DDIM + tid] = fmaf(acc, inv, vQ[(size_t)b * DDIM + tid]);
    for (int i = tid; i < NN; i += 512)
        out_p[(size_t)b * NN + i] *= inv;
}

// ---------------- launch -----------------------------------------------------------
extern "C" void kernel_launch(void* const* d_in, const int* in_sizes, int n_in,
                              void* d_out, int out_size) {
    const float* vI = (const float*)d_in[0];
    const float* vQ = (const float*)d_in[1];
    const float* WI = (const float*)d_in[2];
    const float* WQ = (const float*)d_in[3];
    const float* bQ = (const float*)d_in[4];
    const float* Wp = (const float*)d_in[5];
    // d_in[6] = b_p: cancels under softmax, unused.
    float* out_p = (float*)d_out;
    float* out_u = out_p + (size_t)BB * NN;

    cudaFuncSetAttribute(main_kernel, cudaFuncAttributeMaxDynamicSharedMemorySize, SMEM_TOTAL);

    prep_qatt<<<BB, AATT>>>(vQ, WQ, bQ);
    prep_wit<<<256, 256>>>(WI);
    main_kernel<<<NCTA, 256, SMEM_TOTAL>>>(vI, Wp, out_p);
    reduce_kernel<<<BB, 512>>>(vQ, out_p, out_u);
}

// round 5
// speedup vs baseline: 1.8905x; 1.8905x over previous
#include <cuda_runtime.h>
#include <cuda_fp16.h>
#include <cstdint>

// Problem constants
#define BB   64
#define NN   4096
#define DDIM 512
#define AATT 128
#define TILE 128
#define NTILES 32            // NN / TILE
#define NCTA  2048           // BB * NTILES
#define KCH   8              // DDIM / 64

// ---------------- SMEM layout ----------------------------------------------------
#define SM_WS   0                     // 4 floats: per-warp w sums
#define SM_Q    64                    // 128 floats q_att[b]
#define SM_WP   576                   // 128 floats W_p
#define SM_P    1088                  // 128 floats logit accumulators
#define SM_W    1600                  // 128 floats exp weights
#define SM_A    2176                  // 8 subtiles x 16KB = 128KB (v_I fp16, SW128; MMA + epilogue)
#define SM_B    (SM_A + 131072)       // 2 x 16KB double buffer (W_I^T fp16, SW128)
#define SMEM_TOTAL (SM_B + 32768)     // 166016 bytes -> 1 CTA/SM

// ---------------- device scratch (no allocation allowed) ------------------------
__device__ float g_qatt[BB * AATT];
__device__ __align__(16) unsigned char g_wit[KCH * 16384];   // W_I^T fp16, pre-swizzled
__device__ float g_partial_acc[(size_t)NCTA * DDIM];         // 4 MB
__device__ float g_partial_S[NCTA];

// ---------------- helpers --------------------------------------------------------
__device__ __forceinline__ uint32_t smem_u32(const void* p) {
    uint32_t a;
    asm("{ .reg .u64 t; cvta.to.shared.u64 t, %1; cvt.u32.u64 %0, t; }" : "=r"(a) : "l"(p));
    return a;
}
__device__ __forceinline__ float tanha(float x) {
    float y; asm("tanh.approx.f32 %0, %1;" : "=f"(y) : "f"(x)); return y;
}
__device__ __forceinline__ uint32_t sw128(uint32_t off) { return off ^ ((off >> 3) & 0x70); }

// ---------------- prep kernel (merged -> 3-launch cycle) --------------------------
// blocks 0..63:   q_att[b][a] = tanh(v_Q[b,:] . W_Q[:,a] + b_Q[a])
// blocks 64..319: W_I^T -> fp16 pre-swizzled subtiles (chunk c: rows a x k in [64c,64c+64))
__global__ void prep_kernel(const float* __restrict__ vQ, const float* __restrict__ WQ,
                            const float* __restrict__ bQ, const float* __restrict__ WI) {
    if (blockIdx.x < 64) {
        int b = blockIdx.x, a = threadIdx.x;
        if (a < AATT) {
            const float* vq = vQ + (size_t)b * DDIM;
            float s = bQ[a];
#pragma unroll 8
            for (int k = 0; k < DDIM; ++k) s = fmaf(vq[k], WQ[(size_t)k * AATT + a], s);
            g_qatt[b * AATT + a] = tanhf(s);
        }
    } else {
        int idx = (blockIdx.x - 64) * 256 + threadIdx.x;   // 0..65535
        int k = idx >> 7, a = idx & 127;
        float v = WI[(size_t)k * AATT + a];
        int sub = k >> 6;
        uint32_t off = (uint32_t)(a * 128 + (k & 63) * 2);
        *(__half*)(g_wit + sub * 16384 + sw128(off)) = __float2half_rn(v);
    }
}

// ---------------- main kernel ------------------------------------------------------
__global__ __launch_bounds__(256, 1)
void main_kernel(const float* __restrict__ vI, const float* __restrict__ Wp,
                 float* __restrict__ out_p) {
    extern __shared__ char smem[];
    float* q_s  = (float*)(smem + SM_Q);
    float* wp_s = (float*)(smem + SM_WP);
    float* p_s  = (float*)(smem + SM_P);
    float* w_s  = (float*)(smem + SM_W);
    float* ws4  = (float*)(smem + SM_WS);

    const int tid  = threadIdx.x, wid = tid >> 5, lane = tid & 31;
    const int bidx = blockIdx.x;
    const int b    = bidx >> 5;
    const int n0   = (bidx & 31) * TILE;

    if (tid < AATT) {
        q_s[tid]  = g_qatt[b * AATT + tid];
        wp_s[tid] = Wp[tid];
        p_s[tid]  = 0.f;
    }

    // Per-thread A-load mapping: thread t loads row = t/2, 32 contiguous floats
    const int arow = tid >> 1, ahalf = tid & 1;
    const float* asrc = vI + ((size_t)b * NN + n0 + arow) * DDIM + ahalf * 32;

    // prefetch chunk 0 into registers
    float4 pf[8];
#pragma unroll
    for (int j = 0; j < 8; ++j) pf[j] = ((const float4*)asrc)[j];

    const int wm = wid >> 2, wn = wid & 3;     // 2 (M) x 4 (N) warp grid
    float acc[4][4][4];
#pragma unroll
    for (int mt = 0; mt < 4; ++mt)
#pragma unroll
        for (int nt = 0; nt < 4; ++nt)
#pragma unroll
            for (int r = 0; r < 4; ++r) acc[mt][nt][r] = 0.f;

    const uint32_t sbase = smem_u32(smem);

    // ---- mainloop: 8 K-chunks of 64; A chunks persist (fp16), B double-buffered ----
    for (int c = 0; c < KCH; ++c) {
        // convert + store A chunk c (fp16, SW128, row stride 128B)
        char* adst = smem + SM_A + c * 16384;
#pragma unroll
        for (int j = 0; j < 4; ++j) {
            __half2 h0 = __floats2half2_rn(pf[2*j].x, pf[2*j].y);
            __half2 h1 = __floats2half2_rn(pf[2*j].z, pf[2*j].w);
            __half2 h2 = __floats2half2_rn(pf[2*j+1].x, pf[2*j+1].y);
            __half2 h3 = __floats2half2_rn(pf[2*j+1].z, pf[2*j+1].w);
            uint4 pk;
            pk.x = *(uint32_t*)&h0; pk.y = *(uint32_t*)&h1;
            pk.z = *(uint32_t*)&h2; pk.w = *(uint32_t*)&h3;
            uint32_t off = (uint32_t)(arow * 128 + ahalf * 64 + j * 16);
            *(uint4*)(adst + sw128(off)) = pk;
        }
        // copy B chunk c (pre-swizzled fp16 in global, L2-resident)
        {
            const uint4* bg = (const uint4*)g_wit + c * 1024;
            uint4* bs = (uint4*)(smem + SM_B + (c & 1) * 16384);
#pragma unroll
            for (int it = 0; it < 4; ++it) bs[tid + it * 256] = bg[tid + it * 256];
        }
        __syncthreads();

        // prefetch next A chunk (overlaps with MMAs below)
        if (c < KCH - 1) {
            const float4* nsrc = (const float4*)(asrc + (c + 1) * 64);
#pragma unroll
            for (int j = 0; j < 8; ++j) pf[j] = nsrc[j];
        }

        // MMA over this chunk: 4 k16-steps, fp16 ldmatrix + m16n8k16
        const uint32_t abase = sbase + SM_A + c * 16384;
        const uint32_t bbase = sbase + SM_B + (c & 1) * 16384;
#pragma unroll
        for (int kk = 0; kk < 4; ++kk) {
            uint32_t af[4][4];
#pragma unroll
            for (int mt = 0; mt < 4; ++mt) {
                int r = wm * 64 + mt * 16 + (lane & 15);
                uint32_t off = (uint32_t)(r * 128 + kk * 32 + ((lane >> 4) << 4));
                uint32_t addr = abase + sw128(off);
                asm volatile("ldmatrix.sync.aligned.m8n8.x4.shared.b16 {%0,%1,%2,%3}, [%4];"
                    : "=r"(af[mt][0]), "=r"(af[mt][1]), "=r"(af[mt][2]), "=r"(af[mt][3])
                    : "r"(addr));
            }
            uint32_t bfr[4][2];
#pragma unroll
            for (int nt = 0; nt < 4; ++nt) {
                int n = wn * 32 + nt * 8 + (lane & 7);
                uint32_t off = (uint32_t)(n * 128 + kk * 32 + (((lane >> 3) & 1) << 4));
                uint32_t addr = bbase + sw128(off);
                asm volatile("ldmatrix.sync.aligned.m8n8.x2.shared.b16 {%0,%1}, [%2];"
                    : "=r"(bfr[nt][0]), "=r"(bfr[nt][1]) : "r"(addr));
            }
#pragma unroll
            for (int mt = 0; mt < 4; ++mt)
#pragma unroll
                for (int nt = 0; nt < 4; ++nt)
                    asm volatile(
                        "mma.sync.aligned.m16n8k16.row.col.f32.f16.f16.f32 "
                        "{%0,%1,%2,%3}, {%4,%5,%6,%7}, {%8,%9}, {%0,%1,%2,%3};"
                        : "+f"(acc[mt][nt][0]), "+f"(acc[mt][nt][1]),
                          "+f"(acc[mt][nt][2]), "+f"(acc[mt][nt][3])
                        : "r"(af[mt][0]), "r"(af[mt][1]), "r"(af[mt][2]), "r"(af[mt][3]),
                          "r"(bfr[nt][0]), "r"(bfr[nt][1]));
        }
    }

    // ---- epilogue 1: logits from accumulators -> p_s[row] via quad-reduce + atomics ----
#pragma unroll
    for (int mt = 0; mt < 4; ++mt) {
        float s0 = 0.f, s1 = 0.f;
#pragma unroll
        for (int nt = 0; nt < 4; ++nt) {
            int col = wn * 32 + nt * 8 + (lane & 3) * 2;
            float q0 = q_s[col], q1 = q_s[col + 1];
            float w0 = wp_s[col], w1 = wp_s[col + 1];
            s0 = fmaf(w0, tanha(tanha(acc[mt][nt][0]) + q0), s0);
            s0 = fmaf(w1, tanha(tanha(acc[mt][nt][1]) + q1), s0);
            s1 = fmaf(w0, tanha(tanha(acc[mt][nt][2]) + q0), s1);
            s1 = fmaf(w1, tanha(tanha(acc[mt][nt][3]) + q1), s1);
        }
        s0 += __shfl_xor_sync(0xffffffffu, s0, 1);
        s0 += __shfl_xor_sync(0xffffffffu, s0, 2);
        s1 += __shfl_xor_sync(0xffffffffu, s1, 1);
        s1 += __shfl_xor_sync(0xffffffffu, s1, 2);
        if ((lane & 3) == 0) {
            int r = wm * 64 + mt * 16 + (lane >> 2);
            atomicAdd(&p_s[r], s0);
            atomicAdd(&p_s[r + 8], s1);
        }
    }
    __syncthreads();

    if (tid < 128) {
        float w = __expf(p_s[tid]);          // logits bounded by ||W_p||_1 ~ 9: no max pass
        out_p[(size_t)b * NN + n0 + tid] = w;  // unnormalized; reduce kernel scales
        w_s[tid] = w;
        float s = w;
#pragma unroll
        for (int o = 16; o; o >>= 1) s += __shfl_xor_sync(0xffffffffu, s, o);
        if (lane == 0) ws4[wid] = s;
    }
    __syncthreads();
    if (tid == 0) g_partial_S[bidx] = ws4[0] + ws4[1] + ws4[2] + ws4[3];

    // ---- epilogue 2: weighted v-sum from resident fp16 A tile (all 8 warps) ----
    {
        int d0 = tid * 2;
        int sub = d0 >> 6;                       // which 64-col K-chunk
        uint32_t cb = (uint32_t)((d0 & 63) * 2); // byte col within chunk
        const char* abase = smem + SM_A + sub * 16384;
        float a0 = 0.f, a1 = 0.f;
#pragma unroll 8
        for (int r = 0; r < TILE; ++r) {
            uint32_t off = (uint32_t)(r * 128) + cb;
            __half2 v2 = *(const __half2*)(abase + sw128(off));
            float2 f = __half22float2(v2);
            float w = w_s[r];
            a0 = fmaf(w, f.x, a0);
            a1 = fmaf(w, f.y, a1);
        }
        *(float2*)(g_partial_acc + (size_t)bidx * DDIM + d0) = make_float2(a0, a1);
    }
}

// ---------------- reduce: S, u, normalize p ---------------------------------------
__global__ void reduce_kernel(const float* __restrict__ vQ, float* __restrict__ out_p,
                              float* __restrict__ out_u) {
    int b = blockIdx.x, tid = threadIdx.x;
    __shared__ float sInv;
    if (tid < 32) {
        float s = g_partial_S[b * 32 + tid];
#pragma unroll
        for (int o = 16; o; o >>= 1) s += __shfl_xor_sync(0xffffffffu, s, o);
        if (tid == 0) sInv = 1.0f / s;
    }
    __syncthreads();
    float inv = sInv;
    float acc = 0.f;
#pragma unroll 8
    for (int t = 0; t < 32; ++t)
        acc += g_partial_acc[(size_t)(b * 32 + t) * DDIM + tid];
    out_u[(size_t)b * DDIM + tid] = fmaf(acc, inv, vQ[(size_t)b * DDIM + tid]);
    for (int i = tid; i < NN; i += 512)
        out_p[(size_t)b * NN + i] *= inv;
}

// ---------------- launch -----------------------------------------------------------
extern "C" void kernel_launch(void* const* d_in, const int* in_sizes, int n_in,
                              void* d_out, int out_size) {
    const float* vI = (const float*)d_in[0];
    const float* vQ = (const float*)d_in[1];
    const float* WI = (const float*)d_in[2];
    const float* WQ = (const float*)d_in[3];
    const float* bQ = (const float*)d_in[4];
    const float* Wp = (const float*)d_in[5];
    // d_in[6] = b_p: cancels under softmax, unused.
    float* out_p = (float*)d_out;
    float* out_u = out_p + (size_t)BB * NN;

    cudaFuncSetAttribute(main_kernel, cudaFuncAttributeMaxDynamicSharedMemorySize, SMEM_TOTAL);

    prep_kernel<<<320, 256>>>(vQ, WQ, bQ, WI);
    main_kernel<<<NCTA, 256, SMEM_TOTAL>>>(vI, Wp, out_p);
    reduce_kernel<<<BB, 512>>>(vQ, out_p, out_u);
}

// round 6
// speedup vs baseline: 2.3041x; 1.2188x over previous
#include <cuda_runtime.h>
#include <cuda_fp16.h>
#include <cstdint>

// Problem constants
#define BB   64
#define NN   4096
#define DDIM 512
#define AATT 128
#define TILE 128
#define NTILES 32            // NN / TILE
#define NCTA  2048           // BB * NTILES
#define KCH   8              // DDIM / 64

// ---------------- SMEM layout ----------------------------------------------------
#define SM_WS   0                     // 16 floats: per-warp w sums
#define SM_Q    64                    // 128 floats q_att[b]
#define SM_WP   576                   // 128 floats W_p
#define SM_P    1088                  // 128 floats logit accumulators
#define SM_W    1600                  // 128 floats exp weights
#define SM_A    2176                  // 8 subtiles x 16KB = 128KB (v_I fp16, SW128; MMA + epilogue)
#define SM_B    (SM_A + 131072)       // 2 x 16KB double buffer (W_I^T fp16, SW128)
#define SMEM_TOTAL (SM_B + 32768)     // 166016 bytes -> 1 CTA/SM

// ---------------- device scratch (no allocation allowed) ------------------------
__device__ float g_qatt[BB * AATT];
__device__ __align__(16) unsigned char g_wit[KCH * 16384];   // W_I^T fp16, pre-swizzled
__device__ float g_partial_acc[(size_t)NCTA * DDIM];         // 4 MB
__device__ float g_partial_S[NCTA];

// ---------------- helpers --------------------------------------------------------
__device__ __forceinline__ uint32_t smem_u32(const void* p) {
    uint32_t a;
    asm("{ .reg .u64 t; cvta.to.shared.u64 t, %1; cvt.u32.u64 %0, t; }" : "=r"(a) : "l"(p));
    return a;
}
__device__ __forceinline__ float tanha(float x) {
    float y; asm("tanh.approx.f32 %0, %1;" : "=f"(y) : "f"(x)); return y;
}
__device__ __forceinline__ uint32_t sw128(uint32_t off) { return off ^ ((off >> 3) & 0x70); }

// ---------------- prep kernel -----------------------------------------------------
// blocks 0..63   (512 thr): q_att[b][a] = tanh(v_Q[b,:] . W_Q[:,a] + b_Q[a]), 4-way k-split
// blocks 64..191 (512 thr): W_I^T -> fp16 pre-swizzled subtiles
__global__ __launch_bounds__(512)
void prep_kernel(const float* __restrict__ vQ, const float* __restrict__ WQ,
                 const float* __restrict__ bQ, const float* __restrict__ WI) {
    int tid = threadIdx.x;
    if (blockIdx.x < 64) {
        int b = blockIdx.x;
        int a = tid >> 2, kq = tid & 3;
        const float* vq = vQ + (size_t)b * DDIM + kq * 128;
        const float* wq = WQ + (size_t)kq * 128 * AATT + a;
        float s0 = 0.f, s1 = 0.f, s2 = 0.f, s3 = 0.f;
#pragma unroll 8
        for (int k = 0; k < 128; k += 4) {
            s0 = fmaf(vq[k],     wq[(size_t)(k)     * AATT], s0);
            s1 = fmaf(vq[k + 1], wq[(size_t)(k + 1) * AATT], s1);
            s2 = fmaf(vq[k + 2], wq[(size_t)(k + 2) * AATT], s2);
            s3 = fmaf(vq[k + 3], wq[(size_t)(k + 3) * AATT], s3);
        }
        float s = (s0 + s1) + (s2 + s3);
        s += __shfl_xor_sync(0xffffffffu, s, 1);
        s += __shfl_xor_sync(0xffffffffu, s, 2);
        if (kq == 0) g_qatt[b * AATT + a] = tanhf(s + bQ[a]);
    } else {
        int idx = (blockIdx.x - 64) * 512 + tid;   // 0..65535
        int k = idx >> 7, a = idx & 127;
        float v = WI[(size_t)k * AATT + a];
        int sub = k >> 6;
        uint32_t off = (uint32_t)(a * 128 + (k & 63) * 2);
        *(__half*)(g_wit + sub * 16384 + sw128(off)) = __float2half_rn(v);
    }
}

// ---------------- main kernel ------------------------------------------------------
__global__ __launch_bounds__(512, 1)
void main_kernel(const float* __restrict__ vI, const float* __restrict__ Wp,
                 float* __restrict__ out_p) {
    extern __shared__ char smem[];
    float* q_s  = (float*)(smem + SM_Q);
    float* wp_s = (float*)(smem + SM_WP);
    float* p_s  = (float*)(smem + SM_P);
    float* w_s  = (float*)(smem + SM_W);
    float* ws4  = (float*)(smem + SM_WS);

    const int tid  = threadIdx.x, wid = tid >> 5, lane = tid & 31;
    const int bidx = blockIdx.x;
    const int b    = bidx >> 5;
    const int n0   = (bidx & 31) * TILE;

    if (tid < AATT) {
        q_s[tid]  = g_qatt[b * AATT + tid];
        wp_s[tid] = Wp[tid];
        p_s[tid]  = 0.f;
    }

    // A-load mapping: thread t -> row = t/4, 16 contiguous floats (quarter t%4)
    const int arow = tid >> 2, aq = tid & 3;
    const float* asrc = vI + ((size_t)b * NN + n0 + arow) * DDIM + aq * 16;

    // prefetch chunk 0 (A into pf, B into pb)
    float4 pf[4];
#pragma unroll
    for (int j = 0; j < 4; ++j) pf[j] = ((const float4*)asrc)[j];
    uint4 pb[2];
    {
        const uint4* bg = (const uint4*)g_wit;
#pragma unroll
        for (int j = 0; j < 2; ++j) pb[j] = bg[tid + j * 512];
    }

    const int wm = wid >> 2, wn = wid & 3;     // 4 (M) x 4 (N) warp grid, warp = 32x32
    float acc[2][4][4];
#pragma unroll
    for (int mt = 0; mt < 2; ++mt)
#pragma unroll
        for (int nt = 0; nt < 4; ++nt)
#pragma unroll
            for (int r = 0; r < 4; ++r) acc[mt][nt][r] = 0.f;

    const uint32_t sbase = smem_u32(smem);

    // ---- mainloop: 8 K-chunks of 64; A chunks persist (fp16), B double-buffered ----
    for (int c = 0; c < KCH; ++c) {
        // store A chunk c from regs (fp16, SW128, row stride 128B)
        char* adst = smem + SM_A + c * 16384;
#pragma unroll
        for (int j = 0; j < 2; ++j) {
            __half2 h0 = __floats2half2_rn(pf[2*j].x, pf[2*j].y);
            __half2 h1 = __floats2half2_rn(pf[2*j].z, pf[2*j].w);
            __half2 h2 = __floats2half2_rn(pf[2*j+1].x, pf[2*j+1].y);
            __half2 h3 = __floats2half2_rn(pf[2*j+1].z, pf[2*j+1].w);
            uint4 pk;
            pk.x = *(uint32_t*)&h0; pk.y = *(uint32_t*)&h1;
            pk.z = *(uint32_t*)&h2; pk.w = *(uint32_t*)&h3;
            uint32_t off = (uint32_t)(arow * 128 + aq * 32 + j * 16);
            *(uint4*)(adst + sw128(off)) = pk;
        }
        // store B chunk c from regs
        {
            uint4* bs = (uint4*)(smem + SM_B + (c & 1) * 16384);
#pragma unroll
            for (int j = 0; j < 2; ++j) bs[tid + j * 512] = pb[j];
        }
        __syncthreads();

        // prefetch next chunk (overlaps with MMAs below)
        if (c < KCH - 1) {
            const float4* nsrc = (const float4*)(asrc + (c + 1) * 64);
#pragma unroll
            for (int j = 0; j < 4; ++j) pf[j] = nsrc[j];
            const uint4* bg = (const uint4*)g_wit + (c + 1) * 1024;
#pragma unroll
            for (int j = 0; j < 2; ++j) pb[j] = bg[tid + j * 512];
        }

        // MMA over this chunk: 4 k16-steps, fp16 ldmatrix + m16n8k16
        const uint32_t abase = sbase + SM_A + c * 16384;
        const uint32_t bbase = sbase + SM_B + (c & 1) * 16384;
#pragma unroll
        for (int kk = 0; kk < 4; ++kk) {
            uint32_t af[2][4];
#pragma unroll
            for (int mt = 0; mt < 2; ++mt) {
                int r = wm * 32 + mt * 16 + (lane & 15);
                uint32_t off = (uint32_t)(r * 128 + kk * 32 + ((lane >> 4) << 4));
                uint32_t addr = abase + sw128(off);
                asm volatile("ldmatrix.sync.aligned.m8n8.x4.shared.b16 {%0,%1,%2,%3}, [%4];"
                    : "=r"(af[mt][0]), "=r"(af[mt][1]), "=r"(af[mt][2]), "=r"(af[mt][3])
                    : "r"(addr));
            }
            uint32_t bfr[4][2];
#pragma unroll
            for (int nt = 0; nt < 4; ++nt) {
                int n = wn * 32 + nt * 8 + (lane & 7);
                uint32_t off = (uint32_t)(n * 128 + kk * 32 + (((lane >> 3) & 1) << 4));
                uint32_t addr = bbase + sw128(off);
                asm volatile("ldmatrix.sync.aligned.m8n8.x2.shared.b16 {%0,%1}, [%2];"
                    : "=r"(bfr[nt][0]), "=r"(bfr[nt][1]) : "r"(addr));
            }
#pragma unroll
            for (int mt = 0; mt < 2; ++mt)
#pragma unroll
                for (int nt = 0; nt < 4; ++nt)
                    asm volatile(
                        "mma.sync.aligned.m16n8k16.row.col.f32.f16.f16.f32 "
                        "{%0,%1,%2,%3}, {%4,%5,%6,%7}, {%8,%9}, {%0,%1,%2,%3};"
                        : "+f"(acc[mt][nt][0]), "+f"(acc[mt][nt][1]),
                          "+f"(acc[mt][nt][2]), "+f"(acc[mt][nt][3])
                        : "r"(af[mt][0]), "r"(af[mt][1]), "r"(af[mt][2]), "r"(af[mt][3]),
                          "r"(bfr[nt][0]), "r"(bfr[nt][1]));
        }
    }

    // ---- epilogue 1: logits from accumulators -> p_s[row] via quad-reduce + atomics ----
#pragma unroll
    for (int mt = 0; mt < 2; ++mt) {
        float s0 = 0.f, s1 = 0.f;
#pragma unroll
        for (int nt = 0; nt < 4; ++nt) {
            int col = wn * 32 + nt * 8 + (lane & 3) * 2;
            float q0 = q_s[col], q1 = q_s[col + 1];
            float w0 = wp_s[col], w1 = wp_s[col + 1];
            s0 = fmaf(w0, tanha(tanha(acc[mt][nt][0]) + q0), s0);
            s0 = fmaf(w1, tanha(tanha(acc[mt][nt][1]) + q1), s0);
            s1 = fmaf(w0, tanha(tanha(acc[mt][nt][2]) + q0), s1);
            s1 = fmaf(w1, tanha(tanha(acc[mt][nt][3]) + q1), s1);
        }
        s0 += __shfl_xor_sync(0xffffffffu, s0, 1);
        s0 += __shfl_xor_sync(0xffffffffu, s0, 2);
        s1 += __shfl_xor_sync(0xffffffffu, s1, 1);
        s1 += __shfl_xor_sync(0xffffffffu, s1, 2);
        if ((lane & 3) == 0) {
            int r = wm * 32 + mt * 16 + (lane >> 2);
            atomicAdd(&p_s[r], s0);
            atomicAdd(&p_s[r + 8], s1);
        }
    }
    __syncthreads();

    if (tid < 128) {
        float w = __expf(p_s[tid]);          // logits bounded by ||W_p||_1 ~ 9: no max pass
        out_p[(size_t)b * NN + n0 + tid] = w;  // unnormalized; reduce kernel scales
        w_s[tid] = w;
        float s = w;
#pragma unroll
        for (int o = 16; o; o >>= 1) s += __shfl_xor_sync(0xffffffffu, s, o);
        if (lane == 0) ws4[wid] = s;
    }
    __syncthreads();
    if (tid == 0) g_partial_S[bidx] = ws4[0] + ws4[1] + ws4[2] + ws4[3];

    // ---- epilogue 2: weighted v-sum from resident fp16 A tile (512 threads, 1 col each) ----
    {
        int d0 = tid;
        int sub = d0 >> 6;                       // which 64-col K-chunk
        uint32_t cb = (uint32_t)((d0 & 63) * 2); // byte col within chunk
        const char* abase = smem + SM_A + sub * 16384;
        float a0 = 0.f;
#pragma unroll 8
        for (int r = 0; r < TILE; ++r) {
            uint32_t off = (uint32_t)(r * 128) + cb;
            __half v = *(const __half*)(abase + sw128(off));
            a0 = fmaf(w_s[r], __half2float(v), a0);
        }
        g_partial_acc[(size_t)bidx * DDIM + d0] = a0;
    }
}

// ---------------- reduce: S, u, normalize p ---------------------------------------
// blocks 0..63:   per-b S + u
// blocks 64..319: normalize p (4 blocks per b, 1024 elements each)
__global__ __launch_bounds__(512)
void reduce_kernel(const float* __restrict__ vQ, float* __restrict__ out_p,
                   float* __restrict__ out_u) {
    int tid = threadIdx.x;
    if (blockIdx.x < 64) {
        int b = blockIdx.x;
        __shared__ float sInv;
        if (tid < 32) {
            float s = g_partial_S[b * 32 + tid];
#pragma unroll
            for (int o = 16; o; o >>= 1) s += __shfl_xor_sync(0xffffffffu, s, o);
            if (tid == 0) sInv = 1.0f / s;
        }
        __syncthreads();
        float inv = sInv;
        float acc = 0.f;
#pragma unroll 8
        for (int t = 0; t < 32; ++t)
            acc += g_partial_acc[(size_t)(b * 32 + t) * DDIM + tid];
        out_u[(size_t)b * DDIM + tid] = fmaf(acc, inv, vQ[(size_t)b * DDIM + tid]);
    } else {
        int blk = blockIdx.x - 64;
        int b = blk >> 2, q = blk & 3;
        float s = g_partial_S[b * 32 + (tid & 31)];
#pragma unroll
        for (int o = 16; o; o >>= 1) s += __shfl_xor_sync(0xffffffffu, s, o);
        float inv = 1.0f / s;
        int base = b * NN + q * 1024;
#pragma unroll
        for (int i = 0; i < 2; ++i)
            out_p[(size_t)base + tid + i * 512] *= inv;
    }
}

// ---------------- launch -----------------------------------------------------------
extern "C" void kernel_launch(void* const* d_in, const int* in_sizes, int n_in,
                              void* d_out, int out_size) {
    const float* vI = (const float*)d_in[0];
    const float* vQ = (const float*)d_in[1];
    const float* WI = (const float*)d_in[2];
    const float* WQ = (const float*)d_in[3];
    const float* bQ = (const float*)d_in[4];
    const float* Wp = (const float*)d_in[5];
    // d_in[6] = b_p: cancels under softmax, unused.
    float* out_p = (float*)d_out;
    float* out_u = out_p + (size_t)BB * NN;

    cudaFuncSetAttribute(main_kernel, cudaFuncAttributeMaxDynamicSharedMemorySize, SMEM_TOTAL);

    prep_kernel<<<192, 512>>>(vQ, WQ, bQ, WI);
    main_kernel<<<NCTA, 512, SMEM_TOTAL>>>(vI, Wp, out_p);
    reduce_kernel<<<320, 512>>>(vQ, out_p, out_u);
}